// round 12
// baseline (speedup 1.0000x reference)
#include <cuda_runtime.h>
#include <cstdint>
#include <math_constants.h>

#define D        64
#define KC       512
#define NCHUNK   64          // 8-code chunks over all 512 codes
#define MT       128         // rows per tile
#define TILES    2048        // 262144 / 128
#define NROWS    262144
#define TPB      256
#define GRID     148
#define XSTRIDE  68

// margin: 2 * 2^-10 * 0.05 * sum|x|  + absolute slop (accum + ref-rounding noise)
#define MARG_COEF 1.9531e-4f
#define MARG_ABS  4.0e-4f

// ---- smem layout (float offsets) ----
#define OFF_X     0                          // 128 x 68 fp32 original X tile
#define OFF_EH    (MT * XSTRIDE)             // 8704: hh frag pack, 64*4*32 float4 = 32768 f
#define OFF_NRM   (OFF_EH + 32768)           // 512
#define OFF_RSQ   (OFF_NRM + KC)             // 128
#define OFF_MARG  (OFF_RSQ + MT)             // 128
#define OFF_BK    (OFF_MARG + MT)            // 128 (int)
#define OFF_K2    (OFF_BK + MT)              // 128 (int)
#define OFF_FLAG  (OFF_K2 + MT)              // 128 (int)
#define OFF_LCNT  (OFF_FLAG + MT)            // 1 (int)
#define OFF_LIST  (OFF_LCNT + 1)             // 128 (int)
#define OFF_WSUM  (OFF_LIST + MT)            // 8
#define SM_FLOATS (OFF_WSUM + 8)
#define SM_BYTES  (SM_FLOATS * 4)            // ~171 KB

__device__ float        g_cta[GRID];
__device__ unsigned int g_done = 0;

__device__ __forceinline__ float to_tf32(float v) {
    uint32_t u;
    asm("cvt.rn.tf32.f32 %0, %1;" : "=r"(u) : "f"(v));
    return __uint_as_float(u);
}

__device__ __forceinline__ void mma_tf32(float& c0, float& c1, float& c2, float& c3,
                                         float a0, float a1, float a2, float a3,
                                         float b0, float b1) {
    asm volatile(
        "mma.sync.aligned.m16n8k8.row.col.f32.tf32.tf32.f32 "
        "{%0,%1,%2,%3}, {%4,%5,%6,%7}, {%8,%9}, {%0,%1,%2,%3};"
        : "+f"(c0), "+f"(c1), "+f"(c2), "+f"(c3)
        : "r"(__float_as_uint(a0)), "r"(__float_as_uint(a1)),
          "r"(__float_as_uint(a2)), "r"(__float_as_uint(a3)),
          "r"(__float_as_uint(b0)), "r"(__float_as_uint(b1)));
}

// sorted top-3 insert (strict < : ties keep earlier entry; exact ties always
// end up non-certified, so tie ordering here never decides the output)
#define TOP3_INS(v, k, b1, k1, b2, k2, b3, k3) \
    do { float _v = (v); int _k = (k); \
        if (_v < b1)      { b3 = b2; k3 = k2; b2 = b1; k2 = k1; b1 = _v; k1 = _k; } \
        else if (_v < b2) { b3 = b2; k3 = k2; b2 = _v; k2 = _k; } \
        else if (_v < b3) { b3 = _v; k3 = _k; } \
    } while (0)

__global__ void __launch_bounds__(TPB, 1)
vq_main(const float* __restrict__ x, const float* __restrict__ emb,
        float* __restrict__ out, int out_size) {
    extern __shared__ float sm[];
    const int tid  = threadIdx.x;
    const int wid  = tid >> 5;
    const int lane = tid & 31;
    const int g    = lane >> 2;
    const int tig  = lane & 3;

    float4* EH4   = (float4*)&sm[OFF_EH];
    int*    sBk   = (int*)&sm[OFF_BK];
    int*    sK2   = (int*)&sm[OFF_K2];
    int*    sFlag = (int*)&sm[OFF_FLAG];
    int*    sLCnt = (int*)&sm[OFF_LCNT];
    int*    sList = (int*)&sm[OFF_LIST];

    // ---- one-time: build E hh frag pack + code norms ----
    for (int slot = tid; slot < NCHUNK * 4 * 32; slot += TPB) {
        const int n  = slot >> 7;
        const int s2 = (slot >> 5) & 3;
        const int l  = slot & 31;
        const int lg = l >> 2, lt = l & 3;
        const float* er = emb + (size_t)(n * 8 + lg) * D;
        const int c0 = 16 * s2 + lt;
        EH4[slot] = make_float4(to_tf32(er[c0]), to_tf32(er[c0 + 4]),
                                to_tf32(er[c0 + 8]), to_tf32(er[c0 + 12]));
    }
    for (int k = tid; k < KC; k += TPB) {
        const float* er = emb + (size_t)k * D;
        float s = 0.f;
        #pragma unroll
        for (int d = 0; d < D; d++) s += er[d] * er[d];
        sm[OFF_NRM + k] = s;
    }
    __syncthreads();

    float ctaAcc = 0.f;

    for (int t = blockIdx.x; t < TILES; t += GRID) {
        const float4* xb = (const float4*)(x + (size_t)t * (MT * D));

        // ---- load X tile fp32 (padded stride 68) ----
        #pragma unroll
        for (int it = 0; it < 8; it++) {
            const int i = it * TPB + tid;
            float4 v = xb[i];
            const int r = i >> 4, c4 = i & 15;
            *(float4*)&sm[OFF_X + r * XSTRIDE + c4 * 4] = v;
        }
        if (tid == 0) *sLCnt = 0;
        __syncthreads();

        // ---- per-row rowsq + sum|x| -> margin ----
        if (tid < MT) {
            const int r = tid;
            float rowsq = 0.f, sabs = 0.f;
            #pragma unroll
            for (int i = 0; i < 16; i++) {
                const int c4 = (i + r) & 15;
                float4 v = *(const float4*)&sm[OFF_X + r * XSTRIDE + c4 * 4];
                rowsq += ((v.x * v.x + v.y * v.y) + v.z * v.z) + v.w * v.w;
                sabs  += fabsf(v.x) + fabsf(v.y) + fabsf(v.z) + fabsf(v.w);
            }
            sm[OFF_RSQ + r]  = rowsq;
            sm[OFF_MARG + r] = MARG_COEF * sabs + MARG_ABS;
        }
        __syncthreads();

        // ---- hh MMA pass: each warp 16 rows x 512 codes ----
        {
            const int wb = wid * 16;
            const int r0 = wb + g, r1 = wb + 8 + g;

            float Ah[32];
            #pragma unroll
            for (int s = 0; s < 8; s++) {
                const int c = 8 * s + tig;
                Ah[4*s+0] = to_tf32(sm[OFF_X + r0 * XSTRIDE + c]);
                Ah[4*s+1] = to_tf32(sm[OFF_X + r1 * XSTRIDE + c]);
                Ah[4*s+2] = to_tf32(sm[OFF_X + r0 * XSTRIDE + c + 4]);
                Ah[4*s+3] = to_tf32(sm[OFF_X + r1 * XSTRIDE + c + 4]);
            }
            const float rs0 = sm[OFF_RSQ + r0];
            const float rs1 = sm[OFF_RSQ + r1];

            float b1a = CUDART_INF_F, b2a = CUDART_INF_F, b3a = CUDART_INF_F;
            float b1b = CUDART_INF_F, b2b = CUDART_INF_F, b3b = CUDART_INF_F;
            int k1a = 0, k2a = 0, k3a = 0, k1b = 0, k2b = 0, k3b = 0;

            #pragma unroll 1
            for (int n4 = 0; n4 < NCHUNK / 4; n4++) {
                float C0[4] = {0,0,0,0}, C1[4] = {0,0,0,0};
                float C2[4] = {0,0,0,0}, C3[4] = {0,0,0,0};
                #pragma unroll
                for (int s2 = 0; s2 < 4; s2++) {
                    float4 B0 = EH4[((n4*4+0)*4 + s2) * 32 + lane];
                    float4 B1 = EH4[((n4*4+1)*4 + s2) * 32 + lane];
                    float4 B2 = EH4[((n4*4+2)*4 + s2) * 32 + lane];
                    float4 B3 = EH4[((n4*4+3)*4 + s2) * 32 + lane];
                    mma_tf32(C0[0],C0[1],C0[2],C0[3], Ah[8*s2],Ah[8*s2+1],Ah[8*s2+2],Ah[8*s2+3], B0.x,B0.y);
                    mma_tf32(C1[0],C1[1],C1[2],C1[3], Ah[8*s2],Ah[8*s2+1],Ah[8*s2+2],Ah[8*s2+3], B1.x,B1.y);
                    mma_tf32(C2[0],C2[1],C2[2],C2[3], Ah[8*s2],Ah[8*s2+1],Ah[8*s2+2],Ah[8*s2+3], B2.x,B2.y);
                    mma_tf32(C3[0],C3[1],C3[2],C3[3], Ah[8*s2],Ah[8*s2+1],Ah[8*s2+2],Ah[8*s2+3], B3.x,B3.y);
                    mma_tf32(C0[0],C0[1],C0[2],C0[3], Ah[8*s2+4],Ah[8*s2+5],Ah[8*s2+6],Ah[8*s2+7], B0.z,B0.w);
                    mma_tf32(C1[0],C1[1],C1[2],C1[3], Ah[8*s2+4],Ah[8*s2+5],Ah[8*s2+6],Ah[8*s2+7], B1.z,B1.w);
                    mma_tf32(C2[0],C2[1],C2[2],C2[3], Ah[8*s2+4],Ah[8*s2+5],Ah[8*s2+6],Ah[8*s2+7], B2.z,B2.w);
                    mma_tf32(C3[0],C3[1],C3[2],C3[3], Ah[8*s2+4],Ah[8*s2+5],Ah[8*s2+6],Ah[8*s2+7], B3.z,B3.w);
                }
                #pragma unroll
                for (int j = 0; j < 4; j++) {
                    const int n  = n4 * 4 + j;
                    const float* Cj = (j==0)?C0:(j==1)?C1:(j==2)?C2:C3;
                    const float2 nv = *(const float2*)&sm[OFF_NRM + n * 8 + 2 * tig];
                    const int k0 = n * 8 + 2 * tig;
                    float s00 = (rs0 + nv.x) - 2.0f * Cj[0];
                    float s01 = (rs0 + nv.y) - 2.0f * Cj[1];
                    float s10 = (rs1 + nv.x) - 2.0f * Cj[2];
                    float s11 = (rs1 + nv.y) - 2.0f * Cj[3];
                    TOP3_INS(s00, k0,     b1a,k1a,b2a,k2a,b3a,k3a);
                    TOP3_INS(s01, k0 + 1, b1a,k1a,b2a,k2a,b3a,k3a);
                    TOP3_INS(s10, k0,     b1b,k1b,b2b,k2b,b3b,k3b);
                    TOP3_INS(s11, k0 + 1, b1b,k1b,b2b,k2b,b3b,k3b);
                }
            }

            // merge top-3 across the 4 tig lanes
            #pragma unroll
            for (int off = 1; off <= 2; off <<= 1) {
                float c1 = __shfl_xor_sync(0xffffffffu, b1a, off);
                float c2 = __shfl_xor_sync(0xffffffffu, b2a, off);
                float c3 = __shfl_xor_sync(0xffffffffu, b3a, off);
                int   d1 = __shfl_xor_sync(0xffffffffu, k1a, off);
                int   d2 = __shfl_xor_sync(0xffffffffu, k2a, off);
                int   d3 = __shfl_xor_sync(0xffffffffu, k3a, off);
                TOP3_INS(c1, d1, b1a,k1a,b2a,k2a,b3a,k3a);
                TOP3_INS(c2, d2, b1a,k1a,b2a,k2a,b3a,k3a);
                TOP3_INS(c3, d3, b1a,k1a,b2a,k2a,b3a,k3a);
                c1 = __shfl_xor_sync(0xffffffffu, b1b, off);
                c2 = __shfl_xor_sync(0xffffffffu, b2b, off);
                c3 = __shfl_xor_sync(0xffffffffu, b3b, off);
                d1 = __shfl_xor_sync(0xffffffffu, k1b, off);
                d2 = __shfl_xor_sync(0xffffffffu, k2b, off);
                d3 = __shfl_xor_sync(0xffffffffu, k3b, off);
                TOP3_INS(c1, d1, b1b,k1b,b2b,k2b,b3b,k3b);
                TOP3_INS(c2, d2, b1b,k1b,b2b,k2b,b3b,k3b);
                TOP3_INS(c3, d3, b1b,k1b,b2b,k2b,b3b,k3b);
            }

            if (tig == 0) {
                {
                    const float m = sm[OFF_MARG + r0];
                    int fl = (b2a - b1a > m) ? 0 : (b3a - b1a > m) ? 1 : 2;
                    sBk[r0] = k1a; sK2[r0] = k2a; sFlag[r0] = fl;
                    if (fl == 2) sList[atomicAdd(sLCnt, 1)] = r0;
                }
                {
                    const float m = sm[OFF_MARG + r1];
                    int fl = (b2b - b1b > m) ? 0 : (b3b - b1b > m) ? 1 : 2;
                    sBk[r1] = k1b; sK2[r1] = k2b; sFlag[r1] = fl;
                    if (fl == 2) sList[atomicAdd(sLCnt, 1)] = r1;
                }
            }
        }
        __syncthreads();

        // ---- top-2 fp32 rescore (flag==1) ----
        if (tid < MT && sFlag[tid] == 1) {
            const int r = tid;
            const int ka = sBk[r], kc = sK2[r];
            const float* ea = emb + (size_t)ka * D;
            const float* ec = emb + (size_t)kc * D;
            float da = 0.f, dc = 0.f;
            #pragma unroll 4
            for (int j = 0; j < D; j++) {
                float xv = sm[OFF_X + r * XSTRIDE + j];
                da += xv * ea[j];
                dc += xv * ec[j];
            }
            float sa = (sm[OFF_RSQ + r] + sm[OFF_NRM + ka]) - 2.0f * da;
            float sc = (sm[OFF_RSQ + r] + sm[OFF_NRM + kc]) - 2.0f * dc;
            int kw;
            if (sa < sc) kw = ka;
            else if (sc < sa) kw = kc;
            else kw = (ka < kc) ? ka : kc;
            sBk[r] = kw;
        }

        // ---- full fp32 rescan (flag==2, rare): one warp per row ----
        {
            const int L = *sLCnt;
            for (int i = wid; i < L; i += 8) {
                const int r = sList[i];
                float bb = CUDART_INF_F; int bk = 0;
                const float rsq = sm[OFF_RSQ + r];
                for (int c = 0; c < 16; c++) {
                    const int k = lane + 32 * c;
                    const float4* e4 = (const float4*)(emb + (size_t)k * D);
                    float dot = 0.f;
                    #pragma unroll
                    for (int q = 0; q < 16; q++) {
                        float4 ev = e4[q];
                        float4 xv = *(const float4*)&sm[OFF_X + r * XSTRIDE + q * 4];
                        dot += ev.x * xv.x + ev.y * xv.y + ev.z * xv.z + ev.w * xv.w;
                    }
                    float s = (rsq + sm[OFF_NRM + k]) - 2.0f * dot;
                    if (s < bb || (s == bb && k < bk)) { bb = s; bk = k; }
                }
                #pragma unroll
                for (int off = 16; off > 0; off >>= 1) {
                    float ov = __shfl_xor_sync(0xffffffffu, bb, off);
                    int   ok = __shfl_xor_sync(0xffffffffu, bk, off);
                    if (ov < bb || (ov == bb && ok < bk)) { bb = ov; bk = ok; }
                }
                if (lane == 0) sBk[r] = bk;
            }
        }
        __syncthreads();

        // ---- gather + write quantized rows ----
        {
            float4* o4 = (float4*)(out + (size_t)t * (MT * D));
            const float4* e4 = (const float4*)emb;
            #pragma unroll
            for (int i4 = tid; i4 < MT * D / 4; i4 += TPB) {
                const int r = i4 >> 4, dd = i4 & 15;
                o4[i4] = e4[(size_t)sBk[r] * 16 + dd];
            }
        }
        // ---- exact per-row diffsq for losses ----
        if (tid < MT) {
            const int r = tid;
            const float* er = emb + (size_t)sBk[r] * D;
            float acc = 0.f;
            #pragma unroll 4
            for (int j = 0; j < D; j++) {
                const int idx = ((r << 2) + j) & 63;
                float d = sm[OFF_X + r * XSTRIDE + idx] - er[idx];
                acc += d * d;
            }
            #pragma unroll
            for (int off = 16; off > 0; off >>= 1)
                acc += __shfl_down_sync(0xffffffffu, acc, off);
            if ((tid & 31) == 0) sm[OFF_WSUM + (tid >> 5)] = acc;
        }
        __syncthreads();
        if (tid == 0)
            ctaAcc += ((sm[OFF_WSUM] + sm[OFF_WSUM+1]) + sm[OFF_WSUM+2]) + sm[OFF_WSUM+3];
        __syncthreads();
    }

    // ---- fused finalize ----
    if (tid == 0) {
        g_cta[blockIdx.x] = ctaAcc;
        __threadfence();
        unsigned int prev = atomicAdd(&g_done, 1);
        if (prev == GRID - 1) {
            float s = 0.f;
            for (int i = 0; i < GRID; i++) s += g_cta[i];
            float mean = s / (float)((long long)NROWS * D);
            out[out_size - 2] = mean;          // codebook_loss
            out[out_size - 1] = 0.25f * mean;  // commitment_loss (BETA)
            g_done = 0;
        }
    }
}

extern "C" void kernel_launch(void* const* d_in, const int* in_sizes, int n_in,
                              void* d_out, int out_size) {
    const float* x   = (const float*)d_in[0];
    const float* emb = (const float*)d_in[1];
    float* out = (float*)d_out;

    cudaFuncSetAttribute(vq_main, cudaFuncAttributeMaxDynamicSharedMemorySize,
                         SM_BYTES);
    vq_main<<<GRID, TPB, SM_BYTES>>>(x, emb, out, out_size);
}